// round 1
// baseline (speedup 1.0000x reference)
#include <cuda_runtime.h>
#include <cuda_bf16.h>
#include <cstdint>

// Problem constants (fixed shapes for NEG_loss_44461501448871)
#define EMB   256
#define BSZ   4096
#define WSZ   5
#define SSZ   15
#define NPAIR (BSZ * WSZ)   // 20480

// Per-pair partial losses (scratch; allocation-free per harness rules)
__device__ float g_partials[NPAIR];

__device__ __forceinline__ float log_sigmoid_f(float x) {
    // log(sigmoid(x)) = min(x,0) - log1p(exp(-|x|))
    return fminf(x, 0.0f) - log1pf(__expf(-fabsf(x)));
}

__device__ __forceinline__ float dot8(const float4& a0, const float4& a1,
                                      const float4& b0, const float4& b1) {
    float d;
    d  = a0.x * b0.x;
    d  = fmaf(a0.y, b0.y, d);
    d  = fmaf(a0.z, b0.z, d);
    d  = fmaf(a0.w, b0.w, d);
    d  = fmaf(a1.x, b1.x, d);
    d  = fmaf(a1.y, b1.y, d);
    d  = fmaf(a1.z, b1.z, d);
    d  = fmaf(a1.w, b1.w, d);
    return d;
}

__device__ __forceinline__ float warp_sum(float v) {
    #pragma unroll
    for (int m = 16; m > 0; m >>= 1)
        v += __shfl_xor_sync(0xFFFFFFFFu, v, m);
    return v;
}

// One warp per pair. Lane l holds inp elements [4l..4l+4) and [128+4l..128+4l+4)
// via two fully-coalesced float4 loads; 16 gathered rows per pair from L2.
__global__ __launch_bounds__(256) void neg_pairs_kernel(
    const float* __restrict__ in_w,
    const float* __restrict__ out_w,
    const int*   __restrict__ in_lab,     // [B]
    const int*   __restrict__ out_lab,    // [B*W] row-major of [B,W]
    const int*   __restrict__ noise_lab)  // [B*W, S]
{
    const int warp = (blockIdx.x * blockDim.x + threadIdx.x) >> 5;
    const int lane = threadIdx.x & 31;
    if (warp >= NPAIR) return;

    const int n = warp;
    // in_idx = tile(input_labels, W)[n] = input_labels[n % B]
    const int in_idx  = __ldg(&in_lab[n % BSZ]);
    // out = out_labels.reshape(-1)[n]  (row-major [B,W])
    const int out_idx = __ldg(&out_lab[n]);

    const float4* inp4 = reinterpret_cast<const float4*>(in_w + (size_t)in_idx * EMB);
    const float4 a0 = __ldg(&inp4[lane]);
    const float4 a1 = __ldg(&inp4[lane + 32]);

    // Positive pair: log_sigmoid(<inp, out>)
    const float4* o4 = reinterpret_cast<const float4*>(out_w + (size_t)out_idx * EMB);
    float d = dot8(a0, a1, __ldg(&o4[lane]), __ldg(&o4[lane + 32]));
    d = warp_sum(d);
    float acc = log_sigmoid_f(d);

    // Preload the 15 noise labels across lanes, broadcast with shfl inside loop
    const int* nl = noise_lab + (size_t)n * SSZ;
    int my_idx = (lane < SSZ) ? __ldg(&nl[lane]) : 0;

    #pragma unroll
    for (int s = 0; s < SSZ; s++) {
        const int idx = __shfl_sync(0xFFFFFFFFu, my_idx, s);
        const float4* r4 = reinterpret_cast<const float4*>(out_w + (size_t)idx * EMB);
        float dd = dot8(a0, a1, __ldg(&r4[lane]), __ldg(&r4[lane + 32]));
        dd = warp_sum(dd);
        // noise row is negated in the reference: log_sigmoid(-<out_row, inp>)
        acc += log_sigmoid_f(-dd);
    }

    if (lane == 0) g_partials[n] = acc;
}

// Fixed-order deterministic reduction: 1 block, 1024 threads.
__global__ __launch_bounds__(1024) void neg_reduce_kernel(float* __restrict__ out) {
    __shared__ float sm[32];
    float s = 0.0f;
    for (int i = threadIdx.x; i < NPAIR; i += 1024)
        s += g_partials[i];
    s = warp_sum(s);
    const int lane = threadIdx.x & 31;
    const int wid  = threadIdx.x >> 5;
    if (lane == 0) sm[wid] = s;
    __syncthreads();
    if (wid == 0) {
        float v = sm[lane];   // 32 warps -> 32 partials
        v = warp_sum(v);
        if (lane == 0) out[0] = -v / (float)BSZ;
    }
}

extern "C" void kernel_launch(void* const* d_in, const int* in_sizes, int n_in,
                              void* d_out, int out_size) {
    const float* in_w      = (const float*)d_in[0];   // [V, E]
    const float* out_w     = (const float*)d_in[1];   // [V, E]
    const int*   in_lab    = (const int*)d_in[2];     // [B]
    const int*   out_lab   = (const int*)d_in[3];     // [B, W]
    const int*   noise_lab = (const int*)d_in[4];     // [B*W, S]
    (void)in_sizes; (void)n_in; (void)out_size;       // num_sampled (d_in[5]) fixed at S=15

    float* out = (float*)d_out;

    // 20480 pairs, warp per pair, 8 warps (256 threads) per block
    const int blocks = NPAIR / 8;  // 2560
    neg_pairs_kernel<<<blocks, 256>>>(in_w, out_w, in_lab, out_lab, noise_lab);
    neg_reduce_kernel<<<1, 1024>>>(out);
}

// round 2
// speedup vs baseline: 1.0010x; 1.0010x over previous
#include <cuda_runtime.h>
#include <cuda_bf16.h>
#include <cstdint>

// Fixed shapes for NEG_loss_44461501448871
#define EMB    256
#define BSZ    4096
#define WSZ    5
#define SSZ    15
#define NPAIR  (BSZ * WSZ)        // 20480
#define WARPS_PER_BLOCK 8
#define NBLOCKS (NPAIR / WARPS_PER_BLOCK)  // 2560

__device__ float g_block_partials[NBLOCKS];
__device__ unsigned int g_done_count;  // zero-init; last block resets to 0

__device__ __forceinline__ float log_sigmoid_f(float x) {
    // log(sigmoid(x)) = min(x,0) - log1p(exp(-|x|))
    return fminf(x, 0.0f) - log1pf(__expf(-fabsf(x)));
}

__device__ __forceinline__ float dot8(const float4& a0, const float4& a1,
                                      const float4& b0, const float4& b1) {
    float d;
    d  = a0.x * b0.x;
    d  = fmaf(a0.y, b0.y, d);
    d  = fmaf(a0.z, b0.z, d);
    d  = fmaf(a0.w, b0.w, d);
    d  = fmaf(a1.x, b1.x, d);
    d  = fmaf(a1.y, b1.y, d);
    d  = fmaf(a1.z, b1.z, d);
    d  = fmaf(a1.w, b1.w, d);
    return d;
}

__device__ __forceinline__ float warp_sum(float v) {
    #pragma unroll
    for (int m = 16; m > 0; m >>= 1)
        v += __shfl_xor_sync(0xFFFFFFFFu, v, m);
    return v;
}

// One warp per (b,w) pair; 8 warps per block; block-level + grid-level
// deterministic fixed-order reduction fused via last-block pattern.
__global__ __launch_bounds__(256) void neg_fused_kernel(
    const float* __restrict__ in_w,
    const float* __restrict__ out_w,
    const int*   __restrict__ in_lab,     // [B]
    const int*   __restrict__ out_lab,    // [B*W]
    const int*   __restrict__ noise_lab,  // [B*W, S]
    float*       __restrict__ out)
{
    __shared__ float sm_warp[WARPS_PER_BLOCK];
    const int lane = threadIdx.x & 31;
    const int wib  = threadIdx.x >> 5;
    const int n    = blockIdx.x * WARPS_PER_BLOCK + wib;  // pair id, always < NPAIR

    // Indices: in_idx = input_labels[n % B] (tile), out_idx = out_labels[n]
    const int in_idx  = __ldg(&in_lab[n % BSZ]);
    const int out_idx = __ldg(&out_lab[n]);

    const float4* inp4 = reinterpret_cast<const float4*>(in_w + (size_t)in_idx * EMB);
    const float4 a0 = __ldg(&inp4[lane]);
    const float4 a1 = __ldg(&inp4[lane + 32]);

    // Noise labels distributed across lanes, broadcast via shfl
    const int* nl = noise_lab + (size_t)n * SSZ;
    int my_idx = (lane < SSZ) ? __ldg(&nl[lane]) : 0;

    // Lane-partial dots for positive + 15 noise rows (independent -> high MLP)
    float part[SSZ + 1];
    {
        const float4* o4 = reinterpret_cast<const float4*>(out_w + (size_t)out_idx * EMB);
        part[0] = dot8(a0, a1, __ldg(&o4[lane]), __ldg(&o4[lane + 32]));
    }
    #pragma unroll
    for (int s = 0; s < SSZ; s++) {
        const int idx = __shfl_sync(0xFFFFFFFFu, my_idx, s);
        const float4* r4 = reinterpret_cast<const float4*>(out_w + (size_t)idx * EMB);
        part[s + 1] = dot8(a0, a1, __ldg(&r4[lane]), __ldg(&r4[lane + 32]));
    }

    // 16 independent warp reductions (ILP across chains), then log-sigmoid
    float acc = log_sigmoid_f(warp_sum(part[0]));
    #pragma unroll
    for (int s = 0; s < SSZ; s++)
        acc += log_sigmoid_f(-warp_sum(part[s + 1]));  // noise rows negated

    // Block reduce (fixed order -> deterministic)
    if (lane == 0) sm_warp[wib] = acc;
    __syncthreads();

    if (threadIdx.x == 0) {
        float b = sm_warp[0];
        #pragma unroll
        for (int w = 1; w < WARPS_PER_BLOCK; w++) b += sm_warp[w];
        g_block_partials[blockIdx.x] = b;
        __threadfence();
    }
    __syncthreads();

    // Last-block grid reduction
    __shared__ unsigned int s_ticket;
    if (threadIdx.x == 0)
        s_ticket = atomicAdd(&g_done_count, 1u);
    __syncthreads();

    if (s_ticket == NBLOCKS - 1) {
        // Fixed-order strided accumulation: thread t sums g[t], g[t+256], ...
        float s = 0.0f;
        #pragma unroll
        for (int i = 0; i < NBLOCKS / 256; i++)
            s += g_block_partials[threadIdx.x + i * 256];
        s = warp_sum(s);
        if (lane == 0) sm_warp[wib] = s;
        __syncthreads();
        if (threadIdx.x == 0) {
            float t = sm_warp[0];
            #pragma unroll
            for (int w = 1; w < WARPS_PER_BLOCK; w++) t += sm_warp[w];
            out[0] = -t / (float)BSZ;
            g_done_count = 0;  // reset for next graph replay
        }
    }
}

extern "C" void kernel_launch(void* const* d_in, const int* in_sizes, int n_in,
                              void* d_out, int out_size) {
    const float* in_w      = (const float*)d_in[0];   // [V, E]
    const float* out_w     = (const float*)d_in[1];   // [V, E]
    const int*   in_lab    = (const int*)d_in[2];     // [B]
    const int*   out_lab   = (const int*)d_in[3];     // [B, W]
    const int*   noise_lab = (const int*)d_in[4];     // [B*W, S]
    (void)in_sizes; (void)n_in; (void)out_size;

    neg_fused_kernel<<<NBLOCKS, 256>>>(in_w, out_w, in_lab, out_lab, noise_lab,
                                       (float*)d_out);
}

// round 3
// speedup vs baseline: 1.1304x; 1.1293x over previous
#include <cuda_runtime.h>
#include <cuda_bf16.h>
#include <cstdint>

// Fixed shapes for NEG_loss_44461501448871
#define EMB    256
#define BSZ    4096
#define WSZ    5
#define SSZ    15
#define NPAIR  (BSZ * WSZ)        // 20480
#define WARPS_PER_BLOCK 8
#define NBLOCKS (NPAIR / WARPS_PER_BLOCK)  // 2560
#define FULLM  0xFFFFFFFFu

__device__ float g_block_partials[NBLOCKS];
__device__ unsigned int g_done_count;  // zero-init; last block resets

__device__ __forceinline__ float log_sigmoid_f(float x) {
    // log(sigmoid(x)) = min(x,0) - log(1 + exp(-|x|)); fast-math MUFU path.
    // |x| <= ~45 here, so exp(-|x|) in (0,1]: no overflow, adequate precision.
    return fminf(x, 0.0f) - __logf(1.0f + __expf(-fabsf(x)));
}

__device__ __forceinline__ float dot8(const float4& a0, const float4& a1,
                                      const float4& b0, const float4& b1) {
    float d;
    d  = a0.x * b0.x;
    d  = fmaf(a0.y, b0.y, d);
    d  = fmaf(a0.z, b0.z, d);
    d  = fmaf(a0.w, b0.w, d);
    d  = fmaf(a1.x, b1.x, d);
    d  = fmaf(a1.y, b1.y, d);
    d  = fmaf(a1.z, b1.z, d);
    d  = fmaf(a1.w, b1.w, d);
    return d;
}

__device__ __forceinline__ float warp_sum(float v) {
    #pragma unroll
    for (int m = 16; m > 0; m >>= 1)
        v += __shfl_xor_sync(FULLM, v, m);
    return v;
}

// One warp per (b,w) pair; 16 gathered rows per pair; 4-row groups reduced by
// a value-exchanging butterfly (6 shfl per 4 sums) with a single log-sigmoid
// per lane per group. Block + grid reduction fused (last-block pattern).
__global__ __launch_bounds__(256) void neg_fused_kernel(
    const float* __restrict__ in_w,
    const float* __restrict__ out_w,
    const int*   __restrict__ in_lab,     // [B]
    const int*   __restrict__ out_lab,    // [B*W]
    const int*   __restrict__ noise_lab,  // [B*W, S]
    float*       __restrict__ out)
{
    __shared__ float sm_warp[WARPS_PER_BLOCK];
    const int lane = threadIdx.x & 31;
    const int wib  = threadIdx.x >> 5;
    const int n    = blockIdx.x * WARPS_PER_BLOCK + wib;  // pair id < NPAIR

    const int in_idx  = __ldg(&in_lab[n % BSZ]);   // tile(input_labels, W)
    const int out_idx = __ldg(&out_lab[n]);

    const float4* inp4 = reinterpret_cast<const float4*>(in_w + (size_t)in_idx * EMB);
    const float4 a0 = __ldg(&inp4[lane]);
    const float4 a1 = __ldg(&inp4[lane + 32]);

    // Noise labels spread across lanes; broadcast by shfl at use.
    const int* nl = noise_lab + (size_t)n * SSZ;
    int my_idx = (lane < SSZ) ? __ldg(&nl[lane]) : 0;

    const bool sel16 = (lane & 16) != 0;
    const bool sel8  = (lane & 8) != 0;

    float acc = 0.0f;
    #pragma unroll
    for (int g = 0; g < 4; g++) {
        // Row dots for this group (noise rows sign-folded: reference negates noise)
        float q[4];
        #pragma unroll
        for (int j = 0; j < 4; j++) {
            const int r = g * 4 + j;
            const int idx = (r == 0) ? out_idx : __shfl_sync(FULLM, my_idx, r - 1);
            const float4* r4 = reinterpret_cast<const float4*>(out_w + (size_t)idx * EMB);
            const float d = dot8(a0, a1, __ldg(&r4[lane]), __ldg(&r4[lane + 32]));
            q[j] = (r == 0) ? d : -d;
        }
        // Butterfly: 4 independent 32-lane sums in 6 shfl; each sum ends on 8 lanes.
        float s0 = sel16 ? q[0] : q[2];
        float s1 = sel16 ? q[1] : q[3];
        float r0 = __shfl_xor_sync(FULLM, s0, 16);
        float r1 = __shfl_xor_sync(FULLM, s1, 16);
        float t0 = (sel16 ? q[2] : q[0]) + r0;
        float t1 = (sel16 ? q[3] : q[1]) + r1;
        float s2 = sel8 ? t0 : t1;
        float r2 = __shfl_xor_sync(FULLM, s2, 8);
        float u  = (sel8 ? t1 : t0) + r2;
        u += __shfl_xor_sync(FULLM, u, 4);
        u += __shfl_xor_sync(FULLM, u, 2);
        u += __shfl_xor_sync(FULLM, u, 1);
        // u = full dot for one of the 4 rows (replicated x8 lanes)
        acc += log_sigmoid_f(u);
    }

    // Each row's logsig counted on 8 lanes -> scale by 1/8.
    const float pair_loss = warp_sum(acc) * 0.125f;

    // Block reduce (fixed order -> deterministic)
    if (lane == 0) sm_warp[wib] = pair_loss;
    __syncthreads();

    if (threadIdx.x == 0) {
        float b = sm_warp[0];
        #pragma unroll
        for (int w = 1; w < WARPS_PER_BLOCK; w++) b += sm_warp[w];
        g_block_partials[blockIdx.x] = b;
        __threadfence();
    }
    __syncthreads();

    // Last-block grid reduction (fixed order)
    __shared__ unsigned int s_ticket;
    if (threadIdx.x == 0)
        s_ticket = atomicAdd(&g_done_count, 1u);
    __syncthreads();

    if (s_ticket == NBLOCKS - 1) {
        float s = 0.0f;
        #pragma unroll
        for (int i = 0; i < NBLOCKS / 256; i++)
            s += g_block_partials[threadIdx.x + i * 256];
        s = warp_sum(s);
        if (lane == 0) sm_warp[wib] = s;
        __syncthreads();
        if (threadIdx.x == 0) {
            float t = sm_warp[0];
            #pragma unroll
            for (int w = 1; w < WARPS_PER_BLOCK; w++) t += sm_warp[w];
            out[0] = -t / (float)BSZ;
            g_done_count = 0;  // reset for next graph replay
        }
    }
}

extern "C" void kernel_launch(void* const* d_in, const int* in_sizes, int n_in,
                              void* d_out, int out_size) {
    const float* in_w      = (const float*)d_in[0];   // [V, E]
    const float* out_w     = (const float*)d_in[1];   // [V, E]
    const int*   in_lab    = (const int*)d_in[2];     // [B]
    const int*   out_lab   = (const int*)d_in[3];     // [B, W]
    const int*   noise_lab = (const int*)d_in[4];     // [B*W, S]
    (void)in_sizes; (void)n_in; (void)out_size;

    neg_fused_kernel<<<NBLOCKS, 256>>>(in_w, out_w, in_lab, out_lab, noise_lab,
                                       (float*)d_out);
}